// round 4
// baseline (speedup 1.0000x reference)
#include <cuda_runtime.h>
#include <cuda_bf16.h>
#include <math.h>
#include <stdint.h>

// ---------------------------------------------------------------------------
// Model dims
// ---------------------------------------------------------------------------
#define DIM   1024
#define FFDIM 4096
#define VOC   32000
#define SEQ   1024
#define BATCH 2
#define MTOK  (BATCH * SEQ)

#define LAYER0_OFF   32768000LL
#define LAYER_STRIDE 16777216LL
#define OFF_LM       (LAYER0_OFF + 2*LAYER_STRIDE)

// ---------------------------------------------------------------------------
// Scratch
// ---------------------------------------------------------------------------
__device__ float g_h  [MTOK * DIM];
__device__ float g_qkv[MTOK * 3 * DIM];
__device__ float g_vt [BATCH * DIM * SEQ];
__device__ float g_s  [BATCH * SEQ * SEQ];
__device__ float g_a  [MTOK * DIM];
__device__ float g_gu [MTOK * 2 * FFDIM];
__device__ float g_t  [MTOK * FFDIM];

// ---------------------------------------------------------------------------
// tf32 helpers (portable mma.sync path — tcgen05 not available on sm_103 target)
// ---------------------------------------------------------------------------
__device__ __forceinline__ uint32_t f2tf32(float x) {
    uint32_t r;
    asm("cvt.rna.tf32.f32 %0, %1;" : "=r"(r) : "f"(x));
    return r;
}

__device__ __forceinline__ void mma16n8k8(float c[4], const uint32_t a[4],
                                          const uint32_t b[2]) {
    asm volatile(
        "mma.sync.aligned.m16n8k8.row.col.f32.tf32.tf32.f32 "
        "{%0,%1,%2,%3}, {%4,%5,%6,%7}, {%8,%9}, {%0,%1,%2,%3};"
        : "+f"(c[0]), "+f"(c[1]), "+f"(c[2]), "+f"(c[3])
        : "r"(a[0]), "r"(a[1]), "r"(a[2]), "r"(a[3]), "r"(b[0]), "r"(b[1]));
}

// ---------------------------------------------------------------------------
// tf32 GEMM: C[M,N] = alpha * A[M,K] @ B[N,K]^T (+ R)
// BM=128, BK=16, BNT in {128, 256}. 256 threads = 8 warps (2 M x 4 N);
// warp tile 64 x (BNT/4). Double-buffered dynamic smem, k-major [BK][BM+8].
// ---------------------------------------------------------------------------
#define BM 128
#define BK 16
#define PAD 8

template<int BNT, int OCC>
__global__ __launch_bounds__(256, OCC)
void tf32_gemm(const float* __restrict__ A, int lda, long long sAz,
               const float* __restrict__ B, int ldb, long long sBz,
               float* __restrict__ C, int ldc, long long sCz,
               const float* __restrict__ R, int K, float alpha)
{
    constexpr int WNI = BNT / 32;   // 8-wide n-fragments per warp
    constexpr int NB  = BNT / 64;   // 64-row chunks in B loader

    extern __shared__ uint32_t smem_raw[];
    uint32_t (*As)[BM + PAD]  = (uint32_t (*)[BM + PAD])  smem_raw;            // [2*BK][]
    uint32_t (*Bs)[BNT + PAD] = (uint32_t (*)[BNT + PAD])(smem_raw + 2 * BK * (BM + PAD));

    const int tid  = threadIdx.x;
    const int warp = tid >> 5, lane = tid & 31;
    const int wm = warp & 1;          // 0..1  (M)
    const int wn = warp >> 1;         // 0..3  (N)
    const int g  = lane >> 2;         // 0..7
    const int tg = lane & 3;          // 0..3

    const long long bz = blockIdx.z;
    A += bz * sAz;  B += bz * sBz;  C += bz * sCz;
    const float* Rp = R ? (R + bz * sCz) : nullptr;
    const int row0 = blockIdx.y * BM;
    const int col0 = blockIdx.x * BNT;

    // global loaders: two A rows + NB B rows per thread, float4 along K
    const int ar = tid >> 2;              // 0..63
    const int ak = (tid & 3) << 2;        // 0,4,8,12
    const float* Ag0 = A + (long long)(row0 + ar) * lda + ak;
    const float* Ag1 = A + (long long)(row0 + ar + 64) * lda + ak;
    const float* Bg[NB];
#pragma unroll
    for (int j = 0; j < NB; j++)
        Bg[j] = B + (long long)(col0 + ar + 64 * j) * ldb + ak;

    float4 va0, va1, vb[NB];

    auto gload = [&](int k0) {
        va0 = *(const float4*)(Ag0 + k0);
        va1 = *(const float4*)(Ag1 + k0);
#pragma unroll
        for (int j = 0; j < NB; j++) vb[j] = *(const float4*)(Bg[j] + k0);
    };
    auto sstore = [&](int buf) {
        const float* f;
        f = (const float*)&va0;
#pragma unroll
        for (int j = 0; j < 4; j++) As[buf * BK + ak + j][ar]      = f2tf32(f[j]);
        f = (const float*)&va1;
#pragma unroll
        for (int j = 0; j < 4; j++) As[buf * BK + ak + j][ar + 64] = f2tf32(f[j]);
#pragma unroll
        for (int jj = 0; jj < NB; jj++) {
            f = (const float*)&vb[jj];
#pragma unroll
            for (int j = 0; j < 4; j++)
                Bs[buf * BK + ak + j][ar + 64 * jj] = f2tf32(f[j]);
        }
    };

    float acc[4][WNI][4];
#pragma unroll
    for (int mi = 0; mi < 4; mi++)
#pragma unroll
        for (int ni = 0; ni < WNI; ni++)
#pragma unroll
            for (int j = 0; j < 4; j++) acc[mi][ni][j] = 0.0f;

    gload(0);
    sstore(0);
    __syncthreads();

    const int NK = K / BK;
    for (int it = 0; it < NK; it++) {
        if (it + 1 < NK) gload((it + 1) * BK);
        const int buf = it & 1;
#pragma unroll
        for (int kk = 0; kk < BK; kk += 8) {
            uint32_t af[4][4], bf[WNI][2];
#pragma unroll
            for (int mi = 0; mi < 4; mi++) {
                int r = wm * 64 + mi * 16 + g;
                af[mi][0] = As[buf * BK + kk + tg][r];
                af[mi][1] = As[buf * BK + kk + tg][r + 8];
                af[mi][2] = As[buf * BK + kk + tg + 4][r];
                af[mi][3] = As[buf * BK + kk + tg + 4][r + 8];
            }
#pragma unroll
            for (int ni = 0; ni < WNI; ni++) {
                int c = wn * (WNI * 8) + ni * 8 + g;
                bf[ni][0] = Bs[buf * BK + kk + tg][c];
                bf[ni][1] = Bs[buf * BK + kk + tg + 4][c];
            }
#pragma unroll
            for (int mi = 0; mi < 4; mi++)
#pragma unroll
                for (int ni = 0; ni < WNI; ni++)
                    mma16n8k8(acc[mi][ni], af[mi], bf[ni]);
        }
        if (it + 1 < NK) {
            sstore((it + 1) & 1);
            __syncthreads();
        }
    }

    // epilogue
#pragma unroll
    for (int mi = 0; mi < 4; mi++) {
        long long r = row0 + wm * 64 + mi * 16 + g;
#pragma unroll
        for (int ni = 0; ni < WNI; ni++) {
            long long c = col0 + wn * (WNI * 8) + ni * 8 + tg * 2;
            float2 v0, v1;
            v0.x = acc[mi][ni][0] * alpha;  v0.y = acc[mi][ni][1] * alpha;
            v1.x = acc[mi][ni][2] * alpha;  v1.y = acc[mi][ni][3] * alpha;
            long long i0 = r * ldc + c;
            long long i1 = (r + 8) * ldc + c;
            if (Rp) {
                float2 r0 = *(const float2*)(Rp + i0);
                float2 r1 = *(const float2*)(Rp + i1);
                v0.x += r0.x; v0.y += r0.y;
                v1.x += r1.x; v1.y += r1.y;
            }
            *(float2*)(C + i0) = v0;
            *(float2*)(C + i1) = v1;
        }
    }
}

#define SMEM_A_BYTES (2 * BK * (BM + PAD) * 4)
#define SMEM_GEMM(BNT) (SMEM_A_BYTES + 2 * BK * ((BNT) + PAD) * 4)

// ---------------------------------------------------------------------------
// Aux kernels
// ---------------------------------------------------------------------------
__global__ void embed_kernel(const int* __restrict__ ids,
                             const float* __restrict__ embed, float* __restrict__ h)
{
    int bs = blockIdx.x;
    long long tok = ids[bs];
    const float4* src = (const float4*)(embed + tok * DIM);
    float4* dst = (float4*)(h + (long long)bs * DIM);
    dst[threadIdx.x] = src[threadIdx.x];
}

__global__ void rope_kernel(float* __restrict__ qkv)
{
    int bs = blockIdx.x;
    int s  = bs & (SEQ - 1);
    int d  = threadIdx.x;                      // 0..511
    float freq = expf(-logf(10000.0f) * ((float)d / 512.0f));
    float sn, cs;
    sincosf((float)s * freq, &sn, &cs);

    float* rq = qkv + (long long)bs * 3072;
    float x1 = rq[d], x2 = rq[d + 512];
    rq[d]       = x1 * cs - x2 * sn;
    rq[d + 512] = x2 * cs + x1 * sn;

    float* rk = rq + 1024;
    x1 = rk[d]; x2 = rk[d + 512];
    rk[d]       = x1 * cs - x2 * sn;
    rk[d + 512] = x2 * cs + x1 * sn;
}

__global__ void transpose_v_kernel(const float* __restrict__ qkv, float* __restrict__ vt)
{
    __shared__ float t[32][33];
    int b = blockIdx.z;
    int s0 = blockIdx.x * 32, d0 = blockIdx.y * 32;
    int s = s0 + threadIdx.y, d = d0 + threadIdx.x;
    t[threadIdx.y][threadIdx.x] = qkv[((long long)b * SEQ + s) * 3072 + 2048 + d];
    __syncthreads();
    int dd = d0 + threadIdx.y, ss = s0 + threadIdx.x;
    vt[((long long)b * DIM + dd) * SEQ + ss] = t[threadIdx.x][threadIdx.y];
}

__global__ void softmax_kernel(float* __restrict__ Sm)
{
    __shared__ float red[256];
    float* row = Sm + (long long)blockIdx.x * SEQ;
    int t = threadIdx.x;
    float4 v = ((float4*)row)[t];
    float m = fmaxf(fmaxf(v.x, v.y), fmaxf(v.z, v.w));
    red[t] = m; __syncthreads();
    for (int w = 128; w > 0; w >>= 1) { if (t < w) red[t] = fmaxf(red[t], red[t + w]); __syncthreads(); }
    m = red[0]; __syncthreads();
    float e0 = expf(v.x - m), e1 = expf(v.y - m), e2 = expf(v.z - m), e3 = expf(v.w - m);
    red[t] = e0 + e1 + e2 + e3; __syncthreads();
    for (int w = 128; w > 0; w >>= 1) { if (t < w) red[t] += red[t + w]; __syncthreads(); }
    float inv = 1.0f / red[0];
    ((float4*)row)[t] = make_float4(e0 * inv, e1 * inv, e2 * inv, e3 * inv);
}

__global__ void silu_mul_kernel(const float* __restrict__ gu, float* __restrict__ t)
{
    long long i = (long long)blockIdx.x * blockDim.x + threadIdx.x;
    long long row = i >> 12;
    int col = (int)(i & 4095);
    float x = gu[row * 8192 + col];
    float u = gu[row * 8192 + 4096 + col];
    t[i] = x / (1.0f + expf(-x)) * u;
}

// ---------------------------------------------------------------------------
// Host side
// ---------------------------------------------------------------------------
static void gemm_big(const float* A, int lda, const float* B, int ldb,
                     float* C, int ldc, const float* R, int M, int N, int K,
                     float alpha)
{
    dim3 grid(N / 256, M / BM, 1);
    tf32_gemm<256, 1><<<grid, 256, SMEM_GEMM(256)>>>(A, lda, 0, B, ldb, 0,
                                                     C, ldc, 0, R, K, alpha);
}
static void gemm_small(const float* A, int lda, long long sAz,
                       const float* B, int ldb, long long sBz,
                       float* C, int ldc, long long sCz,
                       const float* R, int M, int N, int K, float alpha, int bz)
{
    dim3 grid(N / 128, M / BM, bz);
    tf32_gemm<128, 2><<<grid, 256, SMEM_GEMM(128)>>>(A, lda, sAz, B, ldb, sBz,
                                                     C, ldc, sCz, R, K, alpha);
}

extern "C" void kernel_launch(void* const* d_in, const int* in_sizes, int n_in,
                              void* d_out, int out_size)
{
    (void)in_sizes; (void)n_in; (void)out_size;
    const int*   ids    = (const int*)d_in[0];
    const float* blocks = (const float*)d_in[1];
    float*       out    = (float*)d_out;

    static int attr_done = 0;
    if (!attr_done) {
        cudaFuncSetAttribute(tf32_gemm<256, 1>,
                             cudaFuncAttributeMaxDynamicSharedMemorySize, SMEM_GEMM(256));
        cudaFuncSetAttribute(tf32_gemm<128, 2>,
                             cudaFuncAttributeMaxDynamicSharedMemorySize, SMEM_GEMM(128));
        attr_done = 1;
    }

    float *h, *qkv, *vt, *s, *a, *gu, *t;
    cudaGetSymbolAddress((void**)&h,   g_h);
    cudaGetSymbolAddress((void**)&qkv, g_qkv);
    cudaGetSymbolAddress((void**)&vt,  g_vt);
    cudaGetSymbolAddress((void**)&s,   g_s);
    cudaGetSymbolAddress((void**)&a,   g_a);
    cudaGetSymbolAddress((void**)&gu,  g_gu);
    cudaGetSymbolAddress((void**)&t,   g_t);

    const long long SD3 = (long long)SEQ * 3072;
    const long long SD  = (long long)SEQ * DIM;
    const long long SS  = (long long)SEQ * SEQ;

    embed_kernel<<<MTOK, 256>>>(ids, blocks, h);

    for (int l = 0; l < 2; l++) {
        const float* Wqkv = blocks + LAYER0_OFF + (long long)l * LAYER_STRIDE; // [3072,1024]
        const float* Wo   = Wqkv + 3LL * DIM * DIM;
        const float* Wgu  = Wo + (long long)DIM * DIM;                          // [8192,1024]
        const float* Wd   = Wgu + 2LL * FFDIM * DIM;

        // qkv = h @ Wqkv^T (fused q|k|v)
        gemm_big(h, DIM, Wqkv, DIM, qkv, 3 * DIM, nullptr, MTOK, 3 * DIM, DIM, 1.0f);
        rope_kernel<<<MTOK, 512>>>(qkv);
        {
            dim3 gr(SEQ / 32, DIM / 32, BATCH);
            transpose_v_kernel<<<gr, dim3(32, 32)>>>(qkv, vt);
        }
        // scores = scale * q @ k^T (batched)
        gemm_small(qkv, 3 * DIM, SD3, qkv + DIM, 3 * DIM, SD3, s, SEQ, SS,
                   nullptr, SEQ, SEQ, DIM, 1.0f / 32.0f, BATCH);
        softmax_kernel<<<BATCH * SEQ, 256>>>(s);
        // a = attn @ V (NT vs transposed V, batched)
        gemm_small(s, SEQ, SS, vt, SEQ, SD, a, DIM, SD, nullptr,
                   SEQ, DIM, SEQ, 1.0f, BATCH);
        // h = a @ Wo^T + h
        gemm_small(a, DIM, 0, Wo, DIM, 0, h, DIM, 0, h, MTOK, DIM, DIM, 1.0f, 1);
        // gu = h @ [Wg|Wu]^T (fused)
        gemm_big(h, DIM, Wgu, DIM, gu, 2 * FFDIM, nullptr, MTOK, 2 * FFDIM, DIM, 1.0f);
        silu_mul_kernel<<<(MTOK * FFDIM) / 256, 256>>>(gu, t);
        // h = t @ Wd^T + h
        gemm_small(t, FFDIM, 0, Wd, FFDIM, 0, h, DIM, 0, h, MTOK, DIM, FFDIM, 1.0f, 1);
    }

    gemm_big(h, DIM, blocks + OFF_LM, DIM, out, VOC, nullptr, MTOK, VOC, DIM, 1.0f);
}

// round 5
// speedup vs baseline: 1.3806x; 1.3806x over previous
#include <cuda_runtime.h>
#include <cuda_bf16.h>
#include <math.h>
#include <stdint.h>

// ---------------------------------------------------------------------------
// Model dims
// ---------------------------------------------------------------------------
#define DIM   1024
#define FFDIM 4096
#define VOC   32000
#define SEQ   1024
#define BATCH 2
#define MTOK  (BATCH * SEQ)

#define LAYER0_OFF   32768000LL
#define LAYER_STRIDE 16777216LL
#define NWEIGHT      (2 * LAYER_STRIDE + (long long)VOC * DIM)  // 66322432

// ---------------------------------------------------------------------------
// Scratch
// ---------------------------------------------------------------------------
__device__ float g_w  [NWEIGHT];          // tf32-rounded weights (layers + lm)
__device__ float g_h  [MTOK * DIM];
__device__ float g_qkv[MTOK * 3 * DIM];
__device__ float g_vt [BATCH * DIM * SEQ];
__device__ float g_s  [BATCH * SEQ * SEQ];
__device__ float g_a  [MTOK * DIM];
__device__ float g_gu [MTOK * 2 * FFDIM];
__device__ float g_t  [MTOK * FFDIM];

// ---------------------------------------------------------------------------
// helpers
// ---------------------------------------------------------------------------
__device__ __forceinline__ uint32_t f2tf32(float x) {
    uint32_t r;
    asm("cvt.rna.tf32.f32 %0, %1;" : "=r"(r) : "f"(x));
    return r;
}
__device__ __forceinline__ float round_tf32(float x) {
    return __uint_as_float(f2tf32(x));
}

__device__ __forceinline__ uint32_t smem_u32(const void* p) {
    uint32_t a;
    asm("{ .reg .u64 t; cvta.to.shared.u64 t, %1; cvt.u32.u64 %0, t; }" : "=r"(a) : "l"(p));
    return a;
}
#define CP_ASYNC16(dst, src) \
    asm volatile("cp.async.cg.shared.global [%0], [%1], 16;" :: "r"(dst), "l"(src))
#define CP_COMMIT() asm volatile("cp.async.commit_group;" ::: "memory")
#define CP_WAIT(n)  asm volatile("cp.async.wait_group %0;" :: "n"(n) : "memory")

__device__ __forceinline__ void mma16n8k8(float c[4], const uint32_t a[4],
                                          const uint32_t b[2]) {
    asm volatile(
        "mma.sync.aligned.m16n8k8.row.col.f32.tf32.tf32.f32 "
        "{%0,%1,%2,%3}, {%4,%5,%6,%7}, {%8,%9}, {%0,%1,%2,%3};"
        : "+f"(c[0]), "+f"(c[1]), "+f"(c[2]), "+f"(c[3])
        : "r"(a[0]), "r"(a[1]), "r"(a[2]), "r"(a[3]), "r"(b[0]), "r"(b[1]));
}

// ---------------------------------------------------------------------------
// tf32 GEMM, cp.async 4-stage: C[M,N] = alpha * A[M,K] @ B[N,K]^T (+ R)
// Inputs MUST already be tf32-rounded fp32. BM=BN=128, BK=16, 256 thr,
// 8 warps (2M x 4N), warp tile 64x32. SMEM m-major, row stride 20 floats.
// ---------------------------------------------------------------------------
#define BM 128
#define BN 128
#define BK 16
#define RS 20                       // floats per smem row (80B, banks coprime)
#define STG_F   (2 * 128 * RS)      // floats per stage (A then B)
#define B_F     (128 * RS)          // B offset within stage (floats)
#define STAGES  4
#define GEMM_SMEM (STAGES * STG_F * 4)   // 81920 bytes

template<bool ROUNDC>
__global__ __launch_bounds__(256, 2)
void tf32_gemm(const float* __restrict__ A, int lda, long long sAz,
               const float* __restrict__ B, int ldb, long long sBz,
               float* __restrict__ C, int ldc, long long sCz,
               const float* __restrict__ R, int K, float alpha)
{
    extern __shared__ float sm[];
    const uint32_t smb = smem_u32(sm);

    const int tid  = threadIdx.x;
    const int warp = tid >> 5, lane = tid & 31;
    const int wm = warp & 1;
    const int wn = warp >> 1;
    const int g  = lane >> 2;
    const int tg = lane & 3;

    const long long bz = blockIdx.z;
    A += bz * sAz;  B += bz * sBz;  C += bz * sCz;
    const float* Rp = R ? (R + bz * sCz) : nullptr;
    const int row0 = blockIdx.y * BM;
    const int col0 = blockIdx.x * BN;

    // cp.async fill: 1024 16B-chunks (A: 128x4, B: 128x4), 4 per thread
    const int fr = (tid & 127) >> 1;          // reuse per j below
    (void)fr;
    auto fill = [&](int st, int k0) {
        uint32_t base = smb + st * (STG_F * 4);
#pragma unroll
        for (int j = 0; j < 4; j++) {
            int id = tid + 256 * j;           // 0..1023
            int isB = id >> 9;                // 0 for A, 1 for B
            int r  = (id & 511) >> 2;         // 0..127
            int kc = id & 3;                  // 16B chunk within row
            const float* src = (isB ? (B + (long long)(col0 + r) * ldb)
                                    : (A + (long long)(row0 + r) * lda))
                               + k0 + kc * 4;
            uint32_t dst = base + (isB ? B_F * 4 : 0) + r * (RS * 4) + kc * 16;
            CP_ASYNC16(dst, src);
        }
    };

    float acc[4][4][4];
#pragma unroll
    for (int mi = 0; mi < 4; mi++)
#pragma unroll
        for (int ni = 0; ni < 4; ni++)
#pragma unroll
            for (int j = 0; j < 4; j++) acc[mi][ni][j] = 0.0f;

    const int NK = K / BK;
    fill(0, 0);            CP_COMMIT();
    fill(1, BK);           CP_COMMIT();
    fill(2, 2 * BK);       CP_COMMIT();

    for (int it = 0; it < NK; it++) {
        CP_WAIT(2);
        __syncthreads();

        const int st = it & (STAGES - 1);
        const float* sA = sm + st * STG_F;
        const float* sB = sA + B_F;
#pragma unroll
        for (int kk = 0; kk < BK; kk += 8) {
            uint32_t af[4][4], bf[4][2];
#pragma unroll
            for (int mi = 0; mi < 4; mi++) {
                int r = wm * 64 + mi * 16 + g;
                af[mi][0] = __float_as_uint(sA[r * RS + kk + tg]);
                af[mi][1] = __float_as_uint(sA[(r + 8) * RS + kk + tg]);
                af[mi][2] = __float_as_uint(sA[r * RS + kk + tg + 4]);
                af[mi][3] = __float_as_uint(sA[(r + 8) * RS + kk + tg + 4]);
            }
#pragma unroll
            for (int ni = 0; ni < 4; ni++) {
                int c = wn * 32 + ni * 8 + g;
                bf[ni][0] = __float_as_uint(sB[c * RS + kk + tg]);
                bf[ni][1] = __float_as_uint(sB[c * RS + kk + tg + 4]);
            }
#pragma unroll
            for (int mi = 0; mi < 4; mi++)
#pragma unroll
                for (int ni = 0; ni < 4; ni++)
                    mma16n8k8(acc[mi][ni], af[mi], bf[ni]);
        }

        int nf = it + 3;
        if (nf < NK) fill(nf & (STAGES - 1), nf * BK);
        CP_COMMIT();
    }

    // epilogue
#pragma unroll
    for (int mi = 0; mi < 4; mi++) {
        long long r = row0 + wm * 64 + mi * 16 + g;
#pragma unroll
        for (int ni = 0; ni < 4; ni++) {
            long long c = col0 + wn * 32 + ni * 8 + tg * 2;
            float2 v0, v1;
            v0.x = acc[mi][ni][0] * alpha;  v0.y = acc[mi][ni][1] * alpha;
            v1.x = acc[mi][ni][2] * alpha;  v1.y = acc[mi][ni][3] * alpha;
            long long i0 = r * ldc + c;
            long long i1 = (r + 8) * ldc + c;
            if (Rp) {
                float2 r0 = *(const float2*)(Rp + i0);
                float2 r1 = *(const float2*)(Rp + i1);
                v0.x += r0.x; v0.y += r0.y;
                v1.x += r1.x; v1.y += r1.y;
            }
            if (ROUNDC) {
                v0.x = round_tf32(v0.x); v0.y = round_tf32(v0.y);
                v1.x = round_tf32(v1.x); v1.y = round_tf32(v1.y);
            }
            *(float2*)(C + i0) = v0;
            *(float2*)(C + i1) = v1;
        }
    }
}

// ---------------------------------------------------------------------------
// Aux kernels (producers round their outputs to tf32)
// ---------------------------------------------------------------------------
__global__ void round_weights_kernel(const float* __restrict__ src,
                                     float* __restrict__ dst)
{
    long long i = ((long long)blockIdx.x * 256 + threadIdx.x) * 4;
    float4 v = *(const float4*)(src + i);
    v.x = round_tf32(v.x); v.y = round_tf32(v.y);
    v.z = round_tf32(v.z); v.w = round_tf32(v.w);
    *(float4*)(dst + i) = v;
}

__global__ void embed_kernel(const int* __restrict__ ids,
                             const float* __restrict__ embed, float* __restrict__ h)
{
    int bs = blockIdx.x;
    long long tok = ids[bs];
    const float4* src = (const float4*)(embed + tok * DIM);
    float4 v = src[threadIdx.x];
    v.x = round_tf32(v.x); v.y = round_tf32(v.y);
    v.z = round_tf32(v.z); v.w = round_tf32(v.w);
    ((float4*)(h + (long long)bs * DIM))[threadIdx.x] = v;
}

__global__ void rope_kernel(float* __restrict__ qkv)
{
    int bs = blockIdx.x;
    int s  = bs & (SEQ - 1);
    int d  = threadIdx.x;                      // 0..511
    float freq = expf(-logf(10000.0f) * ((float)d / 512.0f));
    float sn, cs;
    sincosf((float)s * freq, &sn, &cs);

    float* rq = qkv + (long long)bs * 3072;
    float x1 = rq[d], x2 = rq[d + 512];
    rq[d]       = round_tf32(x1 * cs - x2 * sn);
    rq[d + 512] = round_tf32(x2 * cs + x1 * sn);

    float* rk = rq + 1024;
    x1 = rk[d]; x2 = rk[d + 512];
    rk[d]       = round_tf32(x1 * cs - x2 * sn);
    rk[d + 512] = round_tf32(x2 * cs + x1 * sn);
}

__global__ void transpose_v_kernel(const float* __restrict__ qkv, float* __restrict__ vt)
{
    __shared__ float t[32][33];
    int b = blockIdx.z;
    int s0 = blockIdx.x * 32, d0 = blockIdx.y * 32;
    int s = s0 + threadIdx.y, d = d0 + threadIdx.x;
    t[threadIdx.y][threadIdx.x] = qkv[((long long)b * SEQ + s) * 3072 + 2048 + d];
    __syncthreads();
    int dd = d0 + threadIdx.y, ss = s0 + threadIdx.x;
    vt[((long long)b * DIM + dd) * SEQ + ss] = round_tf32(t[threadIdx.x][threadIdx.y]);
}

__global__ void softmax_kernel(float* __restrict__ Sm)
{
    __shared__ float red[256];
    float* row = Sm + (long long)blockIdx.x * SEQ;
    int t = threadIdx.x;
    float4 v = ((float4*)row)[t];
    float m = fmaxf(fmaxf(v.x, v.y), fmaxf(v.z, v.w));
    red[t] = m; __syncthreads();
    for (int w = 128; w > 0; w >>= 1) { if (t < w) red[t] = fmaxf(red[t], red[t + w]); __syncthreads(); }
    m = red[0]; __syncthreads();
    float e0 = expf(v.x - m), e1 = expf(v.y - m), e2 = expf(v.z - m), e3 = expf(v.w - m);
    red[t] = e0 + e1 + e2 + e3; __syncthreads();
    for (int w = 128; w > 0; w >>= 1) { if (t < w) red[t] += red[t + w]; __syncthreads(); }
    float inv = 1.0f / red[0];
    ((float4*)row)[t] = make_float4(round_tf32(e0 * inv), round_tf32(e1 * inv),
                                    round_tf32(e2 * inv), round_tf32(e3 * inv));
}

__global__ void silu_mul_kernel(const float* __restrict__ gu, float* __restrict__ t)
{
    long long i = (long long)blockIdx.x * blockDim.x + threadIdx.x;
    long long row = i >> 12;
    int col = (int)(i & 4095);
    float x = gu[row * 8192 + col];
    float u = gu[row * 8192 + 4096 + col];
    t[i] = round_tf32(x / (1.0f + expf(-x)) * u);
}

// ---------------------------------------------------------------------------
// Host side
// ---------------------------------------------------------------------------
template<bool ROUNDC>
static void gemm(const float* A, int lda, long long sAz,
                 const float* B, int ldb, long long sBz,
                 float* C, int ldc, long long sCz,
                 const float* R, int M, int N, int K, float alpha, int bz)
{
    dim3 grid(N / BN, M / BM, bz);
    tf32_gemm<ROUNDC><<<grid, 256, GEMM_SMEM>>>(A, lda, sAz, B, ldb, sBz,
                                                C, ldc, sCz, R, K, alpha);
}

extern "C" void kernel_launch(void* const* d_in, const int* in_sizes, int n_in,
                              void* d_out, int out_size)
{
    (void)in_sizes; (void)n_in; (void)out_size;
    const int*   ids    = (const int*)d_in[0];
    const float* blocks = (const float*)d_in[1];
    float*       out    = (float*)d_out;

    static int attr_done = 0;
    if (!attr_done) {
        cudaFuncSetAttribute(tf32_gemm<true>,
                             cudaFuncAttributeMaxDynamicSharedMemorySize, GEMM_SMEM);
        cudaFuncSetAttribute(tf32_gemm<false>,
                             cudaFuncAttributeMaxDynamicSharedMemorySize, GEMM_SMEM);
        attr_done = 1;
    }

    float *w, *h, *qkv, *vt, *s, *a, *gu, *t;
    cudaGetSymbolAddress((void**)&w,   g_w);
    cudaGetSymbolAddress((void**)&h,   g_h);
    cudaGetSymbolAddress((void**)&qkv, g_qkv);
    cudaGetSymbolAddress((void**)&vt,  g_vt);
    cudaGetSymbolAddress((void**)&s,   g_s);
    cudaGetSymbolAddress((void**)&a,   g_a);
    cudaGetSymbolAddress((void**)&gu,  g_gu);
    cudaGetSymbolAddress((void**)&t,   g_t);

    const long long SD3 = (long long)SEQ * 3072;
    const long long SD  = (long long)SEQ * DIM;
    const long long SS  = (long long)SEQ * SEQ;

    // pre-round all weights (layers + lm head) to tf32 once per replay
    round_weights_kernel<<<(int)(NWEIGHT / 4 / 256), 256>>>(blocks + LAYER0_OFF, w);

    embed_kernel<<<MTOK, 256>>>(ids, blocks, h);

    for (int l = 0; l < 2; l++) {
        const float* Wqkv = w + (long long)l * LAYER_STRIDE;  // [3072,1024]
        const float* Wo   = Wqkv + 3LL * DIM * DIM;
        const float* Wgu  = Wo + (long long)DIM * DIM;        // [8192,1024]
        const float* Wd   = Wgu + 2LL * FFDIM * DIM;

        // qkv = h @ Wqkv^T (consumers round)
        gemm<false>(h, DIM, 0, Wqkv, DIM, 0, qkv, 3 * DIM, 0, nullptr,
                    MTOK, 3 * DIM, DIM, 1.0f, 1);
        rope_kernel<<<MTOK, 512>>>(qkv);
        {
            dim3 gr(SEQ / 32, DIM / 32, BATCH);
            transpose_v_kernel<<<gr, dim3(32, 32)>>>(qkv, vt);
        }
        // scores = scale * q @ k^T (softmax rounds)
        gemm<false>(qkv, 3 * DIM, SD3, qkv + DIM, 3 * DIM, SD3, s, SEQ, SS,
                    nullptr, SEQ, SEQ, DIM, 1.0f / 32.0f, BATCH);
        softmax_kernel<<<BATCH * SEQ, 256>>>(s);
        // a = attn @ V  -> feeds o-proj, round
        gemm<true>(s, SEQ, SS, vt, SEQ, SD, a, DIM, SD, nullptr,
                   SEQ, DIM, SEQ, 1.0f, BATCH);
        // h = a @ Wo^T + h -> feeds next GEMMs, round
        gemm<true>(a, DIM, 0, Wo, DIM, 0, h, DIM, 0, h, MTOK, DIM, DIM, 1.0f, 1);
        // gu = h @ [Wg|Wu]^T (silu rounds)
        gemm<false>(h, DIM, 0, Wgu, DIM, 0, gu, 2 * FFDIM, 0, nullptr,
                    MTOK, 2 * FFDIM, DIM, 1.0f, 1);
        silu_mul_kernel<<<(MTOK * FFDIM) / 256, 256>>>(gu, t);
        // h = t @ Wd^T + h -> round
        gemm<true>(t, FFDIM, 0, Wd, FFDIM, 0, h, DIM, 0, h, MTOK, DIM, FFDIM, 1.0f, 1);
    }

    // logits (no rounding of final output)
    gemm<false>(h, DIM, 0, w + 2 * LAYER_STRIDE, DIM, 0, out, VOC, 0, nullptr,
                MTOK, VOC, DIM, 1.0f, 1);
}